// round 12
// baseline (speedup 1.0000x reference)
#include <cuda_runtime.h>
#include <cstdint>
#include <math.h>

// Problem constants
#define BB   8
#define LL   128
#define SS   100
#define TT   100
#define QD   512
#define FD   2048
#define HD   512
#define OD   512

#define KP   224          // padded K for ctx gemm (200 -> 224)

// Scratch (device globals; no allocation APIs allowed)
__device__ float g_q[BB * LL * HD];
__device__ float g_key[BB * (SS + TT) * HD];
__device__ float g_keyT[BB * HD * KP];        // [b][c][j], pads stay 0 (module-zeroed, never written)
__device__ float g_ctx[BB * LL * HD];
__device__ float g_sc[BB * LL * 256];         // scores, 256-stride
__device__ float g_wts[BB * LL * KP];         // [b][l][j], pads written 0 by softmax
__device__ float g_wqT[HD * QD];
__device__ float g_wsT[HD * FD];
__device__ float g_woT[OD * (QD + HD)];

// ---------------------------------------------------------------------------
__device__ __forceinline__ uint32_t s2u(const void* p) {
    uint32_t a;
    asm("{ .reg .u64 t; cvta.to.shared.u64 t, %1; cvt.u32.u64 %0, t; }" : "=r"(a) : "l"(p));
    return a;
}
__device__ __forceinline__ void cp16(uint32_t dst, const void* src) {
    asm volatile("cp.async.cg.shared.global [%0], [%1], 16;" :: "r"(dst), "l"(src));
}
#define CP_COMMIT()  asm volatile("cp.async.commit_group;" ::: "memory")
#define CP_WAITG(n)  asm volatile("cp.async.wait_group %0;" :: "n"(n) : "memory")

#define LDSM4(r, a) \
    asm volatile("ldmatrix.sync.aligned.m8n8.x4.shared.b16 {%0,%1,%2,%3}, [%4];" \
        : "=r"((r)[0]), "=r"((r)[1]), "=r"((r)[2]), "=r"((r)[3]) : "r"(a))

#define MMA_TF32(d, a, b0, b1) \
    asm volatile("mma.sync.aligned.m16n8k8.row.col.f32.tf32.tf32.f32 " \
        "{%0,%1,%2,%3}, {%4,%5,%6,%7}, {%8,%9}, {%0,%1,%2,%3};" \
        : "+f"((d)[0]), "+f"((d)[1]), "+f"((d)[2]), "+f"((d)[3]) \
        : "r"((a)[0]), "r"((a)[1]), "r"((a)[2]), "r"((a)[3]), "r"(b0), "r"(b1))

extern __shared__ __align__(128) float dynsm[];

// ---------------------------------------------------------------------------
// prepAll: weight transposes (tf32 RN) + keybuf pre-bias + scores zero.
// ---------------------------------------------------------------------------
__global__ __launch_bounds__(256) void prepAll(
    const float* __restrict__ Wq, float* __restrict__ wqT,
    const float* __restrict__ Ws, float* __restrict__ wsT,
    const float* __restrict__ Wo, float* __restrict__ woT,
    float* __restrict__ kb, const float* __restrict__ bs,
    float* __restrict__ sc)
{
    int bid = blockIdx.x;
    if (bid < 1792) {
        __shared__ float t[32][33];
        const float* W; float* WT; int K;
        if (bid < 256)       { W = Wq; WT = wqT; K = 512;  }
        else if (bid < 1280) { W = Ws; WT = wsT; K = 2048; bid -= 256;  }
        else                 { W = Wo; WT = woT; K = 1024; bid -= 1280; }
        int k0 = (bid >> 4) * 32, n0 = (bid & 15) * 32;
        int x = threadIdx.x & 31, y = threadIdx.x >> 5;
#pragma unroll
        for (int i = 0; i < 32; i += 8)
            t[y + i][x] = W[(long)(k0 + y + i) * 512 + n0 + x];
        __syncthreads();
#pragma unroll
        for (int i = 0; i < 32; i += 8) {
            float v = t[x][y + i];
            asm("cvt.rna.tf32.f32 %0, %0;" : "+f"(v));
            WT[(long)(n0 + y + i) * K + k0 + x] = v;
        }
        return;
    }
    int i = (bid - 1792) * 256 + threadIdx.x;
    if (i < 204800) { ((float4*)kb)[i] = ((const float4*)bs)[i & 127]; return; }
    i -= 204800;
    if (i < 65536) { float4 z = {0.f, 0.f, 0.f, 0.f}; ((float4*)sc)[i] = z; }
}

// ---------------------------------------------------------------------------
// Generalized batched tf32 mma.sync GEMM (3 descriptors per launch):
//   per batch: C[Mreal, nt*128] (+)= A[Mreal, K] @ B[Nreal, K]^T [+ bias]
//   CTA tile 64x128, 4 warps (warp tile 32x64), BK=32, 3-stage cp.async.
// ---------------------------------------------------------------------------
struct GD {
    const float* A0; const float* A1; int aSplit; int lda; int bsA;
    const float* B0; const float* B1; int bSplit; int ldb; int bsB;
    float* C; int ldc; int bsC;
    const float* bias;
    int Ktot; int kSplit;
    int Mreal; int Nreal;
    int mt; int nt; int batches;
};

#define STG_BYTES 24576u
#define ABASE(s) ((s) * STG_BYTES)
#define BBASE(s) ((s) * STG_BYTES + 8192u)
#define DSMEM_G  73728

__global__ __launch_bounds__(128) void gemm_mma(GD ga, GD gb, GD gc, int nA, int nAB)
{
    GD g; int lbid;
    if (blockIdx.x < (unsigned)nA)        { g = ga; lbid = blockIdx.x; }
    else if (blockIdx.x < (unsigned)nAB)  { g = gb; lbid = blockIdx.x - nA; }
    else                                  { g = gc; lbid = blockIdx.x - nAB; }

    const int tilesTot = g.mt * g.nt * g.batches;
    const int within = lbid % tilesTot;
    const int kz     = lbid / tilesTot;
    const int batch  = within / (g.mt * g.nt);
    const int rem    = within % (g.mt * g.nt);
    const int bm = (rem / g.nt) * 64;
    const int bn = (rem % g.nt) * 128;

    const int Kslice = g.Ktot / g.kSplit;
    const int kOff   = kz * Kslice;
    const int T = Kslice >> 5;

    const int tid  = threadIdx.x;
    const int lane = tid & 31;
    const int wid  = tid >> 5;
    const int wm   = (wid & 1) * 32;
    const int wn   = (wid >> 1) * 64;

    const uint32_t smem = s2u(dynsm);

    const int lr     = lane & 7;
    const int rowoff = ((lane >> 3) & 1) * 8;
    const int coff   = lane >> 4;
    const int arow   = wm + rowoff + lr;
    const int brow   = wn + rowoff + lr;

    float acc[2][8][4];
#pragma unroll
    for (int mi = 0; mi < 2; mi++)
#pragma unroll
        for (int ni = 0; ni < 8; ni++)
#pragma unroll
            for (int j = 0; j < 4; j++) acc[mi][ni][j] = 0.f;

    auto issue_tile = [&](int t, int s) {
        const int k0 = kOff + (t << 5);
#pragma unroll
        for (int i = 0; i < 4; i++) {          // A tile: 64 rows x 8 chunks
            int idx = tid + (i << 7);
            int r = idx >> 3, c = idx & 7;
            uint32_t dst = smem + ABASE(s) + (uint32_t)((r << 3) + (c ^ (r & 7))) * 16u;
            int gr = bm + r; if (gr >= g.Mreal) gr = g.Mreal - 1;
            const float* p = (gr < g.aSplit)
                ? g.A0 + (long)gr * g.lda
                : g.A1 + (long)(gr - g.aSplit) * g.lda;
            cp16(dst, p + (long)batch * g.bsA + k0 + c * 4);
        }
#pragma unroll
        for (int i = 0; i < 8; i++) {          // B tile: 128 rows x 8 chunks
            int idx = tid + (i << 7);
            int r = idx >> 3, c = idx & 7;
            uint32_t dst = smem + BBASE(s) + (uint32_t)((r << 3) + (c ^ (r & 7))) * 16u;
            int gc = bn + r; if (gc >= g.Nreal) gc = g.Nreal - 1;
            const float* p = (gc < g.bSplit)
                ? g.B0 + (long)gc * g.ldb
                : g.B1 + (long)(gc - g.bSplit) * g.ldb;
            cp16(dst, p + (long)batch * g.bsB + k0 + c * 4);
        }
    };

    issue_tile(0, 0); CP_COMMIT();
    issue_tile(1, 1); CP_COMMIT();

    int s = 0;
    for (int t = 0; t < T; t++) {
        CP_WAITG(1);
        __syncthreads();
        int sn = s + 2; if (sn >= 3) sn -= 3;
        if (t + 2 < T) issue_tile(t + 2, sn);
        CP_COMMIT();

        const uint32_t ab = smem + ABASE(s);
        const uint32_t bb = smem + BBASE(s);
#pragma unroll
        for (int ks = 0; ks < 4; ks++) {
            uint32_t a[2][4], bf[4][4];
#pragma unroll
            for (int mi = 0; mi < 2; mi++) {
                uint32_t ad = ab + (uint32_t)(arow + mi * 16) * 128u
                                 + (uint32_t)(((ks << 1) + coff) ^ lr) * 16u;
                LDSM4(a[mi], ad);
            }
#pragma unroll
            for (int ng = 0; ng < 4; ng++) {
                uint32_t bd = bb + (uint32_t)(brow + ng * 16) * 128u
                                 + (uint32_t)(((ks << 1) + coff) ^ lr) * 16u;
                LDSM4(bf[ng], bd);
            }
#pragma unroll
            for (int mi = 0; mi < 2; mi++)
#pragma unroll
                for (int j = 0; j < 4; j++)
                    asm("cvt.rna.tf32.f32 %0, %0;" : "+r"(a[mi][j]));
#pragma unroll
            for (int mi = 0; mi < 2; mi++)
#pragma unroll
                for (int ni = 0; ni < 8; ni++) {
                    int ng = ni >> 1, sel = ni & 1;
                    MMA_TF32(acc[mi][ni], a[mi], bf[ng][sel], bf[ng][sel + 2]);
                }
        }
        if (++s >= 3) s -= 3;
    }

    float* Cb = g.C + (long)batch * g.bsC;
    const int r0 = bm + wm + (lane >> 2);
    const int cb = bn + wn + 2 * (lane & 3);
    if (g.kSplit == 1) {
#pragma unroll
        for (int ni = 0; ni < 8; ni++) {
            int col = cb + ni * 8;
            float2 bv = {0.f, 0.f};
            if (g.bias) bv = *(const float2*)&g.bias[col];
#pragma unroll
            for (int mi = 0; mi < 2; mi++) {
                int r = r0 + mi * 16;
                if (r < g.Mreal) {
                    float2 v0 = { acc[mi][ni][0] + bv.x, acc[mi][ni][1] + bv.y };
                    *(float2*)&Cb[(long)r * g.ldc + col] = v0;
                }
                if (r + 8 < g.Mreal) {
                    float2 v1 = { acc[mi][ni][2] + bv.x, acc[mi][ni][3] + bv.y };
                    *(float2*)&Cb[(long)(r + 8) * g.ldc + col] = v1;
                }
            }
        }
    } else {
#pragma unroll
        for (int ni = 0; ni < 8; ni++) {
            int col = cb + ni * 8;
#pragma unroll
            for (int mi = 0; mi < 2; mi++) {
                int r = r0 + mi * 16;
                if (r < g.Mreal) {
                    atomicAdd(&Cb[(long)r * g.ldc + col],     acc[mi][ni][0]);
                    atomicAdd(&Cb[(long)r * g.ldc + col + 1], acc[mi][ni][1]);
                }
                if (r + 8 < g.Mreal) {
                    atomicAdd(&Cb[(long)(r + 8) * g.ldc + col],     acc[mi][ni][2]);
                    atomicAdd(&Cb[(long)(r + 8) * g.ldc + col + 1], acc[mi][ni][3]);
                }
            }
        }
    }
}

// ---------------------------------------------------------------------------
// postScores: [bid < 896] key transpose -> g_keyT; [bid >= 896] softmax
// ---------------------------------------------------------------------------
__global__ __launch_bounds__(256) void postScores(
    const float* __restrict__ gkey, float* __restrict__ gkeyT,
    const float* __restrict__ gsc,  float* __restrict__ gwts)
{
    const int bid = blockIdx.x;
    if (bid < 896) {
        __shared__ float t[32][33];
        const int b  = bid / 112;
        const int rm = bid % 112;
        const int c0 = (rm / 7) * 32;
        const int j0 = (rm % 7) * 32;
        const int x = threadIdx.x & 31, y = threadIdx.x >> 5;
#pragma unroll
        for (int i = 0; i < 32; i += 8) {
            int j = j0 + y + i; if (j > 199) j = 199;
            int srow = (j < SS) ? b * SS + j : BB * SS + b * TT + (j - SS);
            t[y + i][x] = gkey[(long)srow * HD + c0 + x];
        }
        __syncthreads();
        if (j0 + x < 200) {
#pragma unroll
            for (int i = 0; i < 32; i += 8)
                gkeyT[(long)(b * HD + c0 + y + i) * KP + j0 + x] = t[x][y + i];
        }
        return;
    }

    const int r = (bid - 896) * 8 + (threadIdx.x >> 5);
    const int lane = threadIdx.x & 31;
    const int b = r >> 7, l = r & 127;
    const float* srow = gsc + (long)r * 256;
    float* wrow = gwts + (long)(b * LL + l) * KP;

    const float sc1 = 1.0f / 32.0f;
    const float rs2 = 0.70710678118654752f;

    float vb[4], m = -1e30f;
#pragma unroll
    for (int ii = 0; ii < 4; ii++) {
        int jj = lane + 32 * ii;
        vb[ii] = (jj < SS) ? srow[jj] * sc1 : -1e30f;
        m = fmaxf(m, vb[ii]);
    }
#pragma unroll
    for (int off = 16; off; off >>= 1) m = fmaxf(m, __shfl_xor_sync(0xffffffffu, m, off));
    float sum = 0.f;
#pragma unroll
    for (int ii = 0; ii < 4; ii++) {
        int jj = lane + 32 * ii;
        if (jj < SS) { vb[ii] = __expf(vb[ii] - m); sum += vb[ii]; }
    }
#pragma unroll
    for (int off = 16; off; off >>= 1) sum += __shfl_xor_sync(0xffffffffu, sum, off);
    float inv = rs2 / sum;
#pragma unroll
    for (int ii = 0; ii < 4; ii++) {
        int jj = lane + 32 * ii;
        if (jj < SS) wrow[jj] = vb[ii] * inv;
    }

    m = -1e30f;
#pragma unroll
    for (int ii = 0; ii < 4; ii++) {
        int jj = lane + 32 * ii;
        vb[ii] = (jj < TT) ? -srow[SS + jj] * sc1 : -1e30f;
        m = fmaxf(m, vb[ii]);
    }
#pragma unroll
    for (int off = 16; off; off >>= 1) m = fmaxf(m, __shfl_xor_sync(0xffffffffu, m, off));
    sum = 0.f;
#pragma unroll
    for (int ii = 0; ii < 4; ii++) {
        int jj = lane + 32 * ii;
        if (jj < TT) { vb[ii] = __expf(vb[ii] - m); sum += vb[ii]; }
    }
#pragma unroll
    for (int off = 16; off; off >>= 1) sum += __shfl_xor_sync(0xffffffffu, sum, off);
    inv = -rs2 / sum;                         // minus folded in
#pragma unroll
    for (int ii = 0; ii < 4; ii++) {
        int jj = lane + 32 * ii;
        if (jj < TT)                 wrow[SS + jj] = vb[ii] * inv;
        else if (SS + jj < KP)       wrow[SS + jj] = 0.f;      // zero pads
    }
}

// ---------------------------------------------------------------------------
extern "C" void kernel_launch(void* const* d_in, const int* in_sizes, int n_in,
                              void* d_out, int out_size)
{
    const float* query = (const float*)d_in[0];
    const float* src   = (const float*)d_in[1];
    const float* trg   = (const float*)d_in[2];
    const float* Wq    = (const float*)d_in[3];
    const float* bq    = (const float*)d_in[4];
    const float* Ws    = (const float*)d_in[5];
    const float* bs    = (const float*)d_in[6];
    const float* Wo    = (const float*)d_in[7];
    const float* bo    = (const float*)d_in[8];
    float* out = (float*)d_out;

    float *qbuf, *keybuf, *keyTbuf, *ctxbuf, *scbuf, *wtsbuf, *wqT, *wsT, *woT;
    cudaGetSymbolAddress((void**)&qbuf,    g_q);
    cudaGetSymbolAddress((void**)&keybuf,  g_key);
    cudaGetSymbolAddress((void**)&keyTbuf, g_keyT);
    cudaGetSymbolAddress((void**)&ctxbuf,  g_ctx);
    cudaGetSymbolAddress((void**)&scbuf,   g_sc);
    cudaGetSymbolAddress((void**)&wtsbuf,  g_wts);
    cudaGetSymbolAddress((void**)&wqT,     g_wqT);
    cudaGetSymbolAddress((void**)&wsT,     g_wsT);
    cudaGetSymbolAddress((void**)&woT,     g_woT);

    cudaFuncSetAttribute(gemm_mma, cudaFuncAttributeMaxDynamicSharedMemorySize, DSMEM_G);

    // prep: transposes + keybuf pre-bias + scbuf zero
    prepAll<<<2848, 256>>>(Wq, wqT, Ws, wsT, Wo, woT, keybuf, bs, scbuf);

    // Launch 2: key-proj (ks2, atomic) + q-proj (ks1+bias) + out1 (ks1+bias)
    GD dKey = { src, trg, BB * SS, FD, 0,   wsT, wsT, 1 << 30, FD, 0,
                keybuf, 512, 0,  (const float*)0,  FD, 2,
                BB * (SS + TT), 512,  25, 4, 1 };
    GD dQ   = { query, query, 1 << 30, QD, 0,   wqT, wqT, 1 << 30, QD, 0,
                qbuf, 512, 0,  bq,  QD, 1,  BB * LL, 512,  16, 4, 1 };
    GD dO1  = { query, query, 1 << 30, QD, 0,   woT, woT, 1 << 30, QD + HD, 0,
                out, 512, 0,  bo,  QD, 1,  BB * LL, 512,  16, 4, 1 };
    gemm_mma<<<328, 128, DSMEM_G>>>(dKey, dQ, dO1, 200, 264);

    // scores: batched, C[b][128][256] += q_b @ key_b^T, split-K x2 (64 CTAs)
    GD dSc = { qbuf, qbuf, 1 << 30, HD, LL * HD,
               keybuf, keybuf + (long)BB * SS * HD, SS, HD, SS * HD,
               scbuf, 256, LL * 256,  (const float*)0,  HD, 2,
               LL, SS + TT,  2, 2, BB };
    gemm_mma<<<64, 128, DSMEM_G>>>(dSc, dSc, dSc, 64, 64);

    // key transpose + softmax
    postScores<<<896 + 128, 256>>>(keybuf, keyTbuf, scbuf, wtsbuf);

    // ctx: batched, C[b][128][512] = wts_b @ keyT_b^T, direct store (64 CTAs)
    GD dCtx = { wtsbuf, wtsbuf, 1 << 30, KP, LL * KP,
                keyTbuf, keyTbuf, 1 << 30, KP, HD * KP,
                ctxbuf, 512, LL * HD,  (const float*)0,  KP, 1,
                LL, HD,  2, 4, BB };
    gemm_mma<<<64, 128, DSMEM_G>>>(dCtx, dCtx, dCtx, 64, 64);

    // out2: ctx @ Wo[512:], split-K x2, atomic into out (holds bias + out1)
    GD dO2 = { ctxbuf, ctxbuf, 1 << 30, HD, 0,
               woT + QD, woT + QD, 1 << 30, QD + HD, 0,
               out, 512, 0,  (const float*)0,  HD, 2,  BB * LL, 512,  16, 4, 1 };
    gemm_mma<<<128, 128, DSMEM_G>>>(dO2, dO2, dO2, 128, 128);
}

// round 13
// speedup vs baseline: 1.3455x; 1.3455x over previous
#include <cuda_runtime.h>
#include <cuda_fp16.h>
#include <cstdint>
#include <math.h>

// Problem constants
#define BB   8
#define LL   128
#define SS   100
#define TT   100
#define QD   512
#define FD   2048
#define HD   512
#define OD   512

#define KP   224          // padded K for ctx gemm (200 -> 224)

// Scratch (device globals; no allocation APIs allowed)
__device__ __half g_in_q[BB * LL * QD];       // fp16 copy of query
__device__ __half g_in_s[BB * SS * FD];       // fp16 copy of src
__device__ __half g_in_t[BB * TT * FD];       // fp16 copy of trg
__device__ __half g_q[BB * LL * HD];          // q-proj output (fp16)
__device__ __half g_key[BB * (SS + TT) * HD]; // key-proj output (fp16)
__device__ __half g_keyT[BB * HD * KP];       // [b][c][j], pads stay 0 (module-zeroed)
__device__ __half g_ctx[BB * LL * HD];        // ctx (fp16)
__device__ float  g_sc[BB * LL * 256];        // scores fp32, 256-stride
__device__ __half g_wts[BB * LL * KP];        // [b][l][j] signed weights, pads zeroed
__device__ __half g_wqT[HD * QD];
__device__ __half g_wsT[HD * FD];
__device__ __half g_woT[OD * (QD + HD)];

// ---------------------------------------------------------------------------
__device__ __forceinline__ uint32_t s2u(const void* p) {
    uint32_t a;
    asm("{ .reg .u64 t; cvta.to.shared.u64 t, %1; cvt.u32.u64 %0, t; }" : "=r"(a) : "l"(p));
    return a;
}
__device__ __forceinline__ void cp16(uint32_t dst, const void* src) {
    asm volatile("cp.async.cg.shared.global [%0], [%1], 16;" :: "r"(dst), "l"(src));
}
#define CP_COMMIT()  asm volatile("cp.async.commit_group;" ::: "memory")
#define CP_WAITG(n)  asm volatile("cp.async.wait_group %0;" :: "n"(n) : "memory")

#define LDSM4(r, a) \
    asm volatile("ldmatrix.sync.aligned.m8n8.x4.shared.b16 {%0,%1,%2,%3}, [%4];" \
        : "=r"((r)[0]), "=r"((r)[1]), "=r"((r)[2]), "=r"((r)[3]) : "r"(a))

#define MMA_F16(d, a, b0, b1) \
    asm volatile("mma.sync.aligned.m16n8k16.row.col.f32.f16.f16.f32 " \
        "{%0,%1,%2,%3}, {%4,%5,%6,%7}, {%8,%9}, {%0,%1,%2,%3};" \
        : "+f"((d)[0]), "+f"((d)[1]), "+f"((d)[2]), "+f"((d)[3]) \
        : "r"((a)[0]), "r"((a)[1]), "r"((a)[2]), "r"((a)[3]), "r"(b0), "r"(b1))

extern __shared__ __align__(128) float dynsm[];

// ---------------------------------------------------------------------------
// prepAll:
//   bid < 1792           : weight transposes -> fp16 WT (Wq 256 | Ws 1024 | Wo 512)
//   1792 .. 1792+1856    : input conversion f32 -> f16 (query|src|trg), 8 elems/thread
//   then 256             : scbuf <- 0
// ---------------------------------------------------------------------------
__global__ __launch_bounds__(256) void prepAll(
    const float* __restrict__ Wq, __half* __restrict__ wqT,
    const float* __restrict__ Ws, __half* __restrict__ wsT,
    const float* __restrict__ Wo, __half* __restrict__ woT,
    const float* __restrict__ query, const float* __restrict__ src,
    const float* __restrict__ trg,
    __half* __restrict__ q16, __half* __restrict__ s16, __half* __restrict__ t16,
    float* __restrict__ sc)
{
    int bid = blockIdx.x;
    if (bid < 1792) {
        __shared__ float t[32][33];
        const float* W; __half* WT; int K;
        if (bid < 256)       { W = Wq; WT = wqT; K = 512;  }
        else if (bid < 1280) { W = Ws; WT = wsT; K = 2048; bid -= 256;  }
        else                 { W = Wo; WT = woT; K = 1024; bid -= 1280; }
        int k0 = (bid >> 4) * 32, n0 = (bid & 15) * 32;
        int x = threadIdx.x & 31, y = threadIdx.x >> 5;
#pragma unroll
        for (int i = 0; i < 32; i += 8)
            t[y + i][x] = W[(long)(k0 + y + i) * 512 + n0 + x];
        __syncthreads();
#pragma unroll
        for (int i = 0; i < 32; i += 8)
            WT[(long)(n0 + y + i) * K + k0 + x] = __float2half_rn(t[x][y + i]);
        return;
    }
    int i = (bid - 1792) * 256 + threadIdx.x;     // pair-of-float4 index
    if (i < 475136) {
        const float4* s; __half* d;
        if (i < 65536)       { s = (const float4*)query + i * 2;            d = q16 + i * 8; }
        else if (i < 270336) { int j = i - 65536;  s = (const float4*)src + j * 2; d = s16 + j * 8; }
        else                 { int j = i - 270336; s = (const float4*)trg + j * 2; d = t16 + j * 8; }
        float4 v0 = s[0], v1 = s[1];
        __half2 h[4];
        h[0] = __floats2half2_rn(v0.x, v0.y);
        h[1] = __floats2half2_rn(v0.z, v0.w);
        h[2] = __floats2half2_rn(v1.x, v1.y);
        h[3] = __floats2half2_rn(v1.z, v1.w);
        *(uint4*)d = *(uint4*)h;
        return;
    }
    i -= 475136;
    if (i < 65536) { float4 z = {0.f, 0.f, 0.f, 0.f}; ((float4*)sc)[i] = z; }
}

// ---------------------------------------------------------------------------
// Generalized batched fp16 mma.sync GEMM (3 descriptors per launch):
//   per batch: C[Mreal, nt*64] (+)= A[Mreal, K] @ B[Nreal, K]^T [+ bias]
//   CTA tile 64x64, 4 warps (32x32), BK=32 halves, 3-stage cp.async.
//   smem rows: 32 halves padded to 80B (conflict-free ldmatrix, no XOR).
// ---------------------------------------------------------------------------
struct GD {
    const __half* A0; const __half* A1; int aSplit; int lda; int bsA;
    const __half* B0; const __half* B1; int bSplit; int ldb; int bsB;
    void* C; int ldc; int bsC;
    const float* bias;
    int Ktot; int kSplit; int outHalf;
    int Mreal; int Nreal;
    int mt; int nt; int batches;
};

#define STG_BYTES 10240u
#define ABASE(s) ((s) * STG_BYTES)
#define BBASE(s) ((s) * STG_BYTES + 5120u)
#define DSMEM_G  30720

__global__ __launch_bounds__(128) void gemm_mma(GD ga, GD gb, GD gc, int nA, int nAB)
{
    GD g; int lbid;
    if (blockIdx.x < (unsigned)nA)        { g = ga; lbid = blockIdx.x; }
    else if (blockIdx.x < (unsigned)nAB)  { g = gb; lbid = blockIdx.x - nA; }
    else                                  { g = gc; lbid = blockIdx.x - nAB; }

    const int tilesTot = g.mt * g.nt * g.batches;
    const int within = lbid % tilesTot;
    const int kz     = lbid / tilesTot;
    const int batch  = within / (g.mt * g.nt);
    const int rem    = within % (g.mt * g.nt);
    const int bm = (rem / g.nt) * 64;
    const int bn = (rem % g.nt) * 64;

    const int Kslice = g.Ktot / g.kSplit;
    const int kOff   = kz * Kslice;
    const int T = Kslice >> 5;

    const int tid  = threadIdx.x;
    const int lane = tid & 31;
    const int wid  = tid >> 5;
    const int wm   = (wid & 1) * 32;
    const int wn   = (wid >> 1) * 32;

    const uint32_t smem = s2u(dynsm);

    const int lr     = lane & 7;
    const int rowoff = ((lane >> 3) & 1) * 8;
    const int coff   = lane >> 4;            // 16B chunk select within k16
    const int arow   = wm + rowoff + lr;
    const int brow   = wn + rowoff + lr;

    float acc[2][4][4];
#pragma unroll
    for (int mi = 0; mi < 2; mi++)
#pragma unroll
        for (int ni = 0; ni < 4; ni++)
#pragma unroll
            for (int j = 0; j < 4; j++) acc[mi][ni][j] = 0.f;

    auto issue_tile = [&](int t, int s) {
        const int k0 = kOff + (t << 5);
#pragma unroll
        for (int i = 0; i < 2; i++) {          // A: 64 rows x 4 chunks = 256
            int idx = tid + (i << 7);
            int r = idx >> 2, c = idx & 3;
            uint32_t dst = smem + ABASE(s) + (uint32_t)(r * 80 + c * 16);
            int gr = bm + r; if (gr >= g.Mreal) gr = g.Mreal - 1;
            const __half* p = (gr < g.aSplit)
                ? g.A0 + (long)gr * g.lda
                : g.A1 + (long)(gr - g.aSplit) * g.lda;
            cp16(dst, p + (long)batch * g.bsA + k0 + c * 8);
        }
#pragma unroll
        for (int i = 0; i < 2; i++) {          // B: 64 rows x 4 chunks = 256
            int idx = tid + (i << 7);
            int r = idx >> 2, c = idx & 3;
            uint32_t dst = smem + BBASE(s) + (uint32_t)(r * 80 + c * 16);
            int gc = bn + r; if (gc >= g.Nreal) gc = g.Nreal - 1;
            const __half* p = (gc < g.bSplit)
                ? g.B0 + (long)gc * g.ldb
                : g.B1 + (long)(gc - g.bSplit) * g.ldb;
            cp16(dst, p + (long)batch * g.bsB + k0 + c * 8);
        }
    };

    issue_tile(0, 0); CP_COMMIT();
    issue_tile(1, 1); CP_COMMIT();

    int s = 0;
    for (int t = 0; t < T; t++) {
        CP_WAITG(1);
        __syncthreads();
        int sn = s + 2; if (sn >= 3) sn -= 3;
        if (t + 2 < T) issue_tile(t + 2, sn);
        CP_COMMIT();

        const uint32_t ab = smem + ABASE(s);
        const uint32_t bb = smem + BBASE(s);
#pragma unroll
        for (int ks = 0; ks < 2; ks++) {       // two k16 steps per 32-half tile
            uint32_t a[2][4], bf[2][4];
#pragma unroll
            for (int mi = 0; mi < 2; mi++) {
                uint32_t ad = ab + (uint32_t)((arow + mi * 16) * 80 + ((ks << 1) + coff) * 16);
                LDSM4(a[mi], ad);
            }
#pragma unroll
            for (int ng = 0; ng < 2; ng++) {
                uint32_t bd = bb + (uint32_t)((brow + ng * 16) * 80 + ((ks << 1) + coff) * 16);
                LDSM4(bf[ng], bd);
            }
#pragma unroll
            for (int mi = 0; mi < 2; mi++)
#pragma unroll
                for (int ni = 0; ni < 4; ni++) {
                    int ng = ni >> 1, sel = ni & 1;
                    MMA_F16(acc[mi][ni], a[mi], bf[ng][sel], bf[ng][sel + 2]);
                }
        }
        if (++s >= 3) s -= 3;
    }

    const int r0 = bm + wm + (lane >> 2);
    const int cb = bn + wn + 2 * (lane & 3);
    if (g.kSplit == 1) {
        if (g.outHalf) {
            __half* Cb = (__half*)g.C + (long)batch * g.bsC;
#pragma unroll
            for (int ni = 0; ni < 4; ni++) {
                int col = cb + ni * 8;
                float2 bv = {0.f, 0.f};
                if (g.bias) bv = *(const float2*)&g.bias[col];
#pragma unroll
                for (int mi = 0; mi < 2; mi++) {
                    int r = r0 + mi * 16;
                    if (r < g.Mreal)
                        *(__half2*)&Cb[(long)r * g.ldc + col] =
                            __floats2half2_rn(acc[mi][ni][0] + bv.x, acc[mi][ni][1] + bv.y);
                    if (r + 8 < g.Mreal)
                        *(__half2*)&Cb[(long)(r + 8) * g.ldc + col] =
                            __floats2half2_rn(acc[mi][ni][2] + bv.x, acc[mi][ni][3] + bv.y);
                }
            }
        } else {
            float* Cb = (float*)g.C + (long)batch * g.bsC;
#pragma unroll
            for (int ni = 0; ni < 4; ni++) {
                int col = cb + ni * 8;
                float2 bv = {0.f, 0.f};
                if (g.bias) bv = *(const float2*)&g.bias[col];
#pragma unroll
                for (int mi = 0; mi < 2; mi++) {
                    int r = r0 + mi * 16;
                    if (r < g.Mreal) {
                        float2 v0 = { acc[mi][ni][0] + bv.x, acc[mi][ni][1] + bv.y };
                        *(float2*)&Cb[(long)r * g.ldc + col] = v0;
                    }
                    if (r + 8 < g.Mreal) {
                        float2 v1 = { acc[mi][ni][2] + bv.x, acc[mi][ni][3] + bv.y };
                        *(float2*)&Cb[(long)(r + 8) * g.ldc + col] = v1;
                    }
                }
            }
        }
    } else {
        float* Cb = (float*)g.C + (long)batch * g.bsC;
#pragma unroll
        for (int ni = 0; ni < 4; ni++) {
            int col = cb + ni * 8;
#pragma unroll
            for (int mi = 0; mi < 2; mi++) {
                int r = r0 + mi * 16;
                if (r < g.Mreal) {
                    atomicAdd(&Cb[(long)r * g.ldc + col],     acc[mi][ni][0]);
                    atomicAdd(&Cb[(long)r * g.ldc + col + 1], acc[mi][ni][1]);
                }
                if (r + 8 < g.Mreal) {
                    atomicAdd(&Cb[(long)(r + 8) * g.ldc + col],     acc[mi][ni][2]);
                    atomicAdd(&Cb[(long)(r + 8) * g.ldc + col + 1], acc[mi][ni][3]);
                }
            }
        }
    }
}

// ---------------------------------------------------------------------------
// postScores: [bid < 896] fp16 key transpose -> g_keyT; [bid >= 896] softmax
// ---------------------------------------------------------------------------
__global__ __launch_bounds__(256) void postScores(
    const __half* __restrict__ gkey, __half* __restrict__ gkeyT,
    const float* __restrict__ gsc,  __half* __restrict__ gwts)
{
    const int bid = blockIdx.x;
    if (bid < 896) {
        __shared__ __half t[32][33];
        const int b  = bid / 112;
        const int rm = bid % 112;
        const int c0 = (rm / 7) * 32;
        const int j0 = (rm % 7) * 32;
        const int x = threadIdx.x & 31, y = threadIdx.x >> 5;
#pragma unroll
        for (int i = 0; i < 32; i += 8) {
            int j = j0 + y + i; if (j > 199) j = 199;
            int srow = (j < SS) ? b * SS + j : BB * SS + b * TT + (j - SS);
            t[y + i][x] = gkey[(long)srow * HD + c0 + x];
        }
        __syncthreads();
        if (j0 + x < 200) {
#pragma unroll
            for (int i = 0; i < 32; i += 8)
                gkeyT[(long)(b * HD + c0 + y + i) * KP + j0 + x] = t[x][y + i];
        }
        return;
    }

    const int r = (bid - 896) * 8 + (threadIdx.x >> 5);
    const int lane = threadIdx.x & 31;
    const int b = r >> 7, l = r & 127;
    const float* srow = gsc + (long)r * 256;
    __half* wrow = gwts + (long)(b * LL + l) * KP;

    const float sc1 = 1.0f / 32.0f;
    const float rs2 = 0.70710678118654752f;

    float vb[4], m = -1e30f;
#pragma unroll
    for (int ii = 0; ii < 4; ii++) {
        int jj = lane + 32 * ii;
        vb[ii] = (jj < SS) ? srow[jj] * sc1 : -1e30f;
        m = fmaxf(m, vb[ii]);
    }
#pragma unroll
    for (int off = 16; off; off >>= 1) m = fmaxf(m, __shfl_xor_sync(0xffffffffu, m, off));
    float sum = 0.f;
#pragma unroll
    for (int ii = 0; ii < 4; ii++) {
        int jj = lane + 32 * ii;
        if (jj < SS) { vb[ii] = __expf(vb[ii] - m); sum += vb[ii]; }
    }
#pragma unroll
    for (int off = 16; off; off >>= 1) sum += __shfl_xor_sync(0xffffffffu, sum, off);
    float inv = rs2 / sum;
#pragma unroll
    for (int ii = 0; ii < 4; ii++) {
        int jj = lane + 32 * ii;
        if (jj < SS) wrow[jj] = __float2half_rn(vb[ii] * inv);
    }

    m = -1e30f;
#pragma unroll
    for (int ii = 0; ii < 4; ii++) {
        int jj = lane + 32 * ii;
        vb[ii] = (jj < TT) ? -srow[SS + jj] * sc1 : -1e30f;
        m = fmaxf(m, vb[ii]);
    }
#pragma unroll
    for (int off = 16; off; off >>= 1) m = fmaxf(m, __shfl_xor_sync(0xffffffffu, m, off));
    sum = 0.f;
#pragma unroll
    for (int ii = 0; ii < 4; ii++) {
        int jj = lane + 32 * ii;
        if (jj < TT) { vb[ii] = __expf(vb[ii] - m); sum += vb[ii]; }
    }
#pragma unroll
    for (int off = 16; off; off >>= 1) sum += __shfl_xor_sync(0xffffffffu, sum, off);
    inv = -rs2 / sum;                         // minus folded in
#pragma unroll
    for (int ii = 0; ii < 4; ii++) {
        int jj = lane + 32 * ii;
        if (jj < TT)            wrow[SS + jj] = __float2half_rn(vb[ii] * inv);
        else if (SS + jj < KP)  wrow[SS + jj] = __half(0.f);   // zero pads
    }
}

// ---------------------------------------------------------------------------
extern "C" void kernel_launch(void* const* d_in, const int* in_sizes, int n_in,
                              void* d_out, int out_size)
{
    const float* query = (const float*)d_in[0];
    const float* src   = (const float*)d_in[1];
    const float* trg   = (const float*)d_in[2];
    const float* Wq    = (const float*)d_in[3];
    const float* bq    = (const float*)d_in[4];
    const float* Ws    = (const float*)d_in[5];
    const float* bs    = (const float*)d_in[6];
    const float* Wo    = (const float*)d_in[7];
    const float* bo    = (const float*)d_in[8];
    float* out = (float*)d_out;

    __half *q16, *s16, *t16, *qbuf, *keybuf, *keyTbuf, *ctxbuf, *wtsbuf, *wqT, *wsT, *woT;
    float *scbuf;
    cudaGetSymbolAddress((void**)&q16,     g_in_q);
    cudaGetSymbolAddress((void**)&s16,     g_in_s);
    cudaGetSymbolAddress((void**)&t16,     g_in_t);
    cudaGetSymbolAddress((void**)&qbuf,    g_q);
    cudaGetSymbolAddress((void**)&keybuf,  g_key);
    cudaGetSymbolAddress((void**)&keyTbuf, g_keyT);
    cudaGetSymbolAddress((void**)&ctxbuf,  g_ctx);
    cudaGetSymbolAddress((void**)&scbuf,   g_sc);
    cudaGetSymbolAddress((void**)&wtsbuf,  g_wts);
    cudaGetSymbolAddress((void**)&wqT,     g_wqT);
    cudaGetSymbolAddress((void**)&wsT,     g_wsT);
    cudaGetSymbolAddress((void**)&woT,     g_woT);

    // prep: transposes (fp16) + input conversion + scbuf zero
    prepAll<<<1792 + 1856 + 256, 256>>>(Wq, wqT, Ws, wsT, Wo, woT,
                                        query, src, trg, q16, s16, t16, scbuf);

    // Launch 2: key-proj (ks1, fp16 out+bias) + q-proj (ks1 fp16+bias) + out1 (ks1 f32+bias)
    GD dKey = { s16, t16, BB * SS, FD, 0,   wsT, wsT, 1 << 30, FD, 0,
                keybuf, 512, 0,  bs,  FD, 1, 1,  BB * (SS + TT), 512,  25, 8, 1 };
    GD dQ   = { q16, q16, 1 << 30, QD, 0,   wqT, wqT, 1 << 30, QD, 0,
                qbuf, 512, 0,  bq,  QD, 1, 1,  BB * LL, 512,  16, 8, 1 };
    GD dO1  = { q16, q16, 1 << 30, QD, 0,   woT, woT, 1 << 30, QD + HD, 0,
                out, 512, 0,  bo,  QD, 1, 0,  BB * LL, 512,  16, 8, 1 };
    gemm_mma<<<200 + 128 + 128, 128, DSMEM_G>>>(dKey, dQ, dO1, 200, 328);

    // scores: batched, C[b][128][256] += q_b @ key_b^T, split-K x2 (128 CTAs)
    GD dSc = { qbuf, qbuf, 1 << 30, HD, LL * HD,
               keybuf, keybuf + (long)BB * SS * HD, SS, HD, SS * HD,
               scbuf, 256, LL * 256,  (const float*)0,  HD, 2, 0,
               LL, SS + TT,  2, 4, BB };
    gemm_mma<<<128, 128, DSMEM_G>>>(dSc, dSc, dSc, 128, 128);

    // key transpose (fp16) + softmax
    postScores<<<896 + 128, 256>>>(keybuf, keyTbuf, scbuf, wtsbuf);

    // ctx: batched, C[b][128][512] = wts_b @ keyT_b^T, fp16 direct store (128 CTAs)
    GD dCtx = { wtsbuf, wtsbuf, 1 << 30, KP, LL * KP,
                keyTbuf, keyTbuf, 1 << 30, KP, HD * KP,
                ctxbuf, 512, LL * HD,  (const float*)0,  KP, 1, 1,
                LL, HD,  2, 8, BB };
    gemm_mma<<<128, 128, DSMEM_G>>>(dCtx, dCtx, dCtx, 128, 128);

    // out2: ctx @ Wo[512:], split-K x2, atomic into out (holds bias + out1)
    GD dO2 = { ctxbuf, ctxbuf, 1 << 30, HD, 0,
               woT + QD, woT + QD, 1 << 30, QD + HD, 0,
               out, 512, 0,  (const float*)0,  HD, 2, 0,  BB * LL, 512,  16, 8, 1 };
    gemm_mma<<<256, 128, DSMEM_G>>>(dO2, dO2, dO2, 256, 256);
}